// round 7
// baseline (speedup 1.0000x reference)
#include <cuda_runtime.h>
#include <cuda_bf16.h>
#include <cstdint>

// SimCLR loss, B=4096, D=128, T=0.1.  compute_103-safe (mma.sync bf16).
// Symmetric-GEMM version: only upper-triangular 128x128 tiles of sim=z z^T
// are computed (2080 of 4096). Off-diagonal tile (I,J) contributes its
// exp row-sums to rows of block I AND (via column sums) rows of block J.
// pos pairs = local diagonal of tiles (I, I+32); diag = local diag of (I,I).

#define BDIM 4096
#define N2   8192
#define DDIM 128
#define NBLK 64                  // 128-row blocks
#define NPAIRS 2080              // 64*65/2 upper-tri tiles
#define GRID 148
#define RSB  272                 // smem row stride bytes (128 bf16 + 16B pad)

#define LOG2E10 14.42695040888963f   // 10/ln2

// ---- scratch (__device__ globals; no cudaMalloc allowed) ----
__device__ __nv_bfloat16 g_zb[N2 * DDIM];   // 2 MB normalized bf16 rows
__device__ float g_psum[N2];                // exp row sums (atomic; incl diag)
__device__ float g_diag[N2];
__device__ float g_pos[N2];

// ---- helpers ----
__device__ __forceinline__ uint32_t smem_u32(const void* p) {
    uint32_t a;
    asm("{ .reg .u64 t; cvta.to.shared.u64 t, %1; cvt.u32.u64 %0, t; }"
        : "=r"(a) : "l"(p));
    return a;
}
__device__ __forceinline__ float expt(float s) {   // exp(10*s), shared w/ loss
    float e;
    asm("ex2.approx.ftz.f32 %0, %1;" : "=f"(e) : "f"(s * LOG2E10));
    return e;
}

#define CPA16(dst, src) \
    asm volatile("cp.async.cg.shared.global [%0], [%1], 16;" \
                 :: "r"(dst), "l"(src) : "memory")
#define CPA_COMMIT() asm volatile("cp.async.commit_group;" ::: "memory")
#define CPA_WAIT0()  asm volatile("cp.async.wait_group 0;" ::: "memory")

#define LDSM4(r0, r1, r2, r3, a) \
    asm volatile("ldmatrix.sync.aligned.m8n8.x4.shared.b16 {%0,%1,%2,%3}, [%4];" \
                 : "=r"(r0), "=r"(r1), "=r"(r2), "=r"(r3) : "r"(a))

__device__ __forceinline__ void mma16816(float* d, const uint32_t* a,
                                         uint32_t b0, uint32_t b1) {
    asm volatile(
        "mma.sync.aligned.m16n8k16.row.col.f32.bf16.bf16.f32 "
        "{%0,%1,%2,%3}, {%4,%5,%6,%7}, {%8,%9}, {%0,%1,%2,%3};"
        : "+f"(d[0]), "+f"(d[1]), "+f"(d[2]), "+f"(d[3])
        : "r"(a[0]), "r"(a[1]), "r"(a[2]), "r"(a[3]), "r"(b0), "r"(b1));
}

// ---- SMEM: double-buffered A and B blocks, 128 rows x 272B each ----
#define BLKB  34816
#define SM_A0 0
#define SM_A1 BLKB
#define SM_B0 (2 * BLKB)
#define SM_B1 (3 * BLKB)
#define SM_TOTAL (4 * BLKB)      // 139264

__device__ __forceinline__ void map_tile(int t, int& I, int& J) {
    int i = 0, rem = t;
    while (rem >= NBLK - i) { rem -= NBLK - i; ++i; }
    I = i; J = i + rem;
}

__device__ __forceinline__ void load_blk(uint32_t dst, int blk, int tid) {
    #pragma unroll
    for (int i = 0; i < 8; i++) {
        int idx = tid + i * 256;
        int r = idx >> 4, c = idx & 15;
        CPA16(dst + r * RSB + c * 16,
              g_zb + (size_t)(blk * 128 + r) * DDIM + c * 8);
    }
}

// ---------------------------------------------------------------------------
// Kernel 1: L2 normalize -> bf16 (one warp/row) + zero g_psum.
// ---------------------------------------------------------------------------
__global__ void norm_kernel(const float* __restrict__ xi,
                            const float* __restrict__ xj) {
    int gt = blockIdx.x * blockDim.x + threadIdx.x;
    if (gt < N2) g_psum[gt] = 0.f;

    int row  = blockIdx.x * 8 + (threadIdx.x >> 5);
    int lane = threadIdx.x & 31;
    const float* src = (row < BDIM) ? (xi + (size_t)row * DDIM)
                                    : (xj + (size_t)(row - BDIM) * DDIM);
    float4 v = reinterpret_cast<const float4*>(src)[lane];
    float s = v.x * v.x + v.y * v.y + v.z * v.z + v.w * v.w;
    #pragma unroll
    for (int o = 16; o > 0; o >>= 1) s += __shfl_xor_sync(0xFFFFFFFFu, s, o);
    float inv = 1.0f / fmaxf(sqrtf(s), 1e-12f);
    __nv_bfloat16 o4[4];
    o4[0] = __float2bfloat16(v.x * inv);
    o4[1] = __float2bfloat16(v.y * inv);
    o4[2] = __float2bfloat16(v.z * inv);
    o4[3] = __float2bfloat16(v.w * inv);
    *reinterpret_cast<uint2*>(g_zb + (size_t)row * DDIM + lane * 4) =
        *reinterpret_cast<uint2*>(o4);
}

// ---------------------------------------------------------------------------
// Kernel 2: symmetric HMMA GEMM + fused exp row/col-sum epilogue.
// 148 CTAs; CTA p handles upper-tri tiles [p*2080/148, (p+1)*2080/148).
// 8 warps = 4 row-warps x 2 col-warps; warp tile 32x64.
// ---------------------------------------------------------------------------
__global__ void __launch_bounds__(256, 1) simgemm_kernel() {
    extern __shared__ char smem[];
    const uint32_t sb = smem_u32(smem);
    const int tid  = threadIdx.x;
    const int lane = tid & 31;
    const int w    = tid >> 5;
    const int wr   = w & 3;
    const int wc   = w >> 2;

    const int rrow  = (lane & 7) + ((lane >> 3) & 1) * 8;
    const int csel  = lane >> 4;
    const int rquad = lane >> 2;
    const int cpair = (lane & 3) * 2;

    const int t0 = (int)(((long)blockIdx.x * NPAIRS) / GRID);
    const int t1 = (int)(((long)(blockIdx.x + 1) * NPAIRS) / GRID);

    // preload tile t0 (parity 0)
    int I, J;
    map_tile(t0, I, J);
    load_blk(sb + SM_A0, I, tid);
    load_blk(sb + SM_B0, J, tid);
    CPA_COMMIT();
    CPA_WAIT0();
    __syncthreads();

    for (int t = t0; t < t1; t++) {
        const int q = (t - t0) & 1;
        const uint32_t sbA = sb + (q ? SM_A1 : SM_A0);
        const uint32_t sbB = sb + (q ? SM_B1 : SM_B0);

        // prefetch tile t+1 into the other parity
        if (t + 1 < t1) {
            int In, Jn;
            map_tile(t + 1, In, Jn);
            load_blk(sb + (q ? SM_A0 : SM_A1), In, tid);
            load_blk(sb + (q ? SM_B0 : SM_B1), Jn, tid);
            CPA_COMMIT();
        }

        // ---- MMA: acc = A_I (32 rows) x B_J^T (64 cols) ----
        float acc[2][8][4];
        #pragma unroll
        for (int i = 0; i < 2; i++)
            #pragma unroll
            for (int j = 0; j < 8; j++)
                #pragma unroll
                for (int c = 0; c < 4; c++) acc[i][j][c] = 0.f;

        #pragma unroll
        for (int ks = 0; ks < 8; ks++) {
            uint32_t af[2][4];
            #pragma unroll
            for (int i = 0; i < 2; i++) {
                uint32_t a = sbA + (wr * 32 + i * 16 + rrow) * RSB
                           + (ks * 2 + csel) * 16;
                LDSM4(af[i][0], af[i][1], af[i][2], af[i][3], a);
            }
            uint32_t bf[4][4];
            #pragma unroll
            for (int g = 0; g < 4; g++) {
                uint32_t a = sbB + (wc * 64 + g * 16 + rrow) * RSB
                           + (ks * 2 + csel) * 16;
                LDSM4(bf[g][0], bf[g][1], bf[g][2], bf[g][3], a);
            }
            #pragma unroll
            for (int i = 0; i < 2; i++)
                #pragma unroll
                for (int j = 0; j < 8; j++)
                    mma16816(acc[i][j], af[i],
                             bf[j >> 1][j & 1], bf[j >> 1][(j & 1) + 2]);
        }

        // ---- diag / pos capture (pre-exp); both live on local diagonal ----
        const bool isdiag = (I == J);
        const bool ispos  = (J - I == 32);     // col = row ^ 4096
        if (isdiag || ispos) {
            #pragma unroll
            for (int i = 0; i < 2; i++)
                #pragma unroll
                for (int j = 0; j < 8; j++)
                    #pragma unroll
                    for (int c = 0; c < 4; c++) {
                        int rl = wr * 32 + i * 16 + (c >> 1) * 8 + rquad;
                        int cl = wc * 64 + j * 8 + cpair + (c & 1);
                        if (cl == rl) {
                            float s = acc[i][j][c];
                            if (isdiag) g_diag[I * 128 + rl] = s;
                            if (ispos)  { g_pos[I * 128 + rl] = s;
                                          g_pos[J * 128 + rl] = s; }
                        }
                    }
        }

        // ---- exp in place ----
        #pragma unroll
        for (int i = 0; i < 2; i++)
            #pragma unroll
            for (int j = 0; j < 8; j++)
                #pragma unroll
                for (int c = 0; c < 4; c++)
                    acc[i][j][c] = expt(acc[i][j][c]);

        // ---- row sums -> rows of block I ----
        {
            float r4[4] = {0.f, 0.f, 0.f, 0.f};
            #pragma unroll
            for (int i = 0; i < 2; i++)
                #pragma unroll
                for (int j = 0; j < 8; j++)
                    #pragma unroll
                    for (int c = 0; c < 4; c++)
                        r4[i * 2 + (c >> 1)] += acc[i][j][c];
            #pragma unroll
            for (int qq = 0; qq < 4; qq++) {
                r4[qq] += __shfl_xor_sync(0xFFFFFFFFu, r4[qq], 1);
                r4[qq] += __shfl_xor_sync(0xFFFFFFFFu, r4[qq], 2);
            }
            if ((lane & 3) == 0) {
                #pragma unroll
                for (int qq = 0; qq < 4; qq++) {
                    int rl = wr * 32 + (qq >> 1) * 16 + (qq & 1) * 8 + rquad;
                    atomicAdd(&g_psum[I * 128 + rl], r4[qq]);
                }
            }
        }

        // ---- column sums -> rows of block J (off-diagonal tiles only) ----
        if (!isdiag) {
            #pragma unroll
            for (int j = 0; j < 8; j++)
                #pragma unroll
                for (int cc = 0; cc < 2; cc++) {
                    float s = acc[0][j][cc] + acc[0][j][cc + 2]
                            + acc[1][j][cc] + acc[1][j][cc + 2];
                    s += __shfl_xor_sync(0xFFFFFFFFu, s, 4);
                    s += __shfl_xor_sync(0xFFFFFFFFu, s, 8);
                    s += __shfl_xor_sync(0xFFFFFFFFu, s, 16);
                    if (lane < 4)
                        atomicAdd(&g_psum[J * 128 + wc * 64 + j * 8
                                          + (lane & 3) * 2 + cc], s);
                }
        }

        if (t + 1 < t1) CPA_WAIT0();
        __syncthreads();

        if (t + 1 < t1) map_tile(t + 1, I, J);
    }
}

// ---------------------------------------------------------------------------
// Kernel 3: final scalar reduction.
// ---------------------------------------------------------------------------
__global__ void loss_kernel(float* __restrict__ out) {
    __shared__ float sred[256];
    float s = 0.f;
    for (int r = threadIdx.x; r < N2; r += 256) {
        float denom = g_psum[r] - expt(g_diag[r]);
        s += logf(denom) - g_pos[r] * 10.0f;
    }
    sred[threadIdx.x] = s;
    __syncthreads();
    for (int o = 128; o > 0; o >>= 1) {
        if (threadIdx.x < o) sred[threadIdx.x] += sred[threadIdx.x + o];
        __syncthreads();
    }
    if (threadIdx.x == 0) out[0] = sred[0] / (float)N2;
}

// ---------------------------------------------------------------------------
extern "C" void kernel_launch(void* const* d_in, const int* in_sizes, int n_in,
                              void* d_out, int out_size) {
    const float* xi = (const float*)d_in[0];
    const float* xj = (const float*)d_in[1];
    float* out = (float*)d_out;

    cudaFuncSetAttribute(simgemm_kernel,
                         cudaFuncAttributeMaxDynamicSharedMemorySize, SM_TOTAL);

    norm_kernel<<<N2 / 8, 256>>>(xi, xj);
    simgemm_kernel<<<GRID, 256, SM_TOTAL>>>();
    loss_kernel<<<1, 256>>>(out);
}

// round 10
// speedup vs baseline: 1.3968x; 1.3968x over previous
#include <cuda_runtime.h>
#include <cuda_bf16.h>
#include <cstdint>

// SimCLR loss, B=4096, D=128, T=0.1.  compute_103-safe (mma.sync bf16).
// Full (non-symmetric) GEMM, persistent 148-CTA schedule over 4096 tiles
// of 128x128. A block register-resident per row-block segment; B double-
// buffered. Per-tile exp row-sums accumulate in registers; atomic flush
// once per segment. diag/pos captured on tiles (rb,rb) / (rb, rb^32).

#define BDIM 4096
#define N2   8192
#define DDIM 128
#define NCT  64                  // 128-wide col tiles
#define TOT  4096                // 64 row-blocks x 64 col-tiles
#define GRID 148
#define RSB  272                 // smem row stride bytes (128 bf16 + 16B pad)

#define LOG2E10 14.42695040888963f   // 10/ln2

// ---- scratch (__device__ globals; no cudaMalloc allowed) ----
__device__ __nv_bfloat16 g_zb[N2 * DDIM];   // 2 MB normalized bf16 rows
__device__ float g_psum[N2];                // exp row sums (atomic; incl diag)
__device__ float g_diag[N2];
__device__ float g_pos[N2];

// ---- helpers ----
__device__ __forceinline__ uint32_t smem_u32(const void* p) {
    uint32_t a;
    asm("{ .reg .u64 t; cvta.to.shared.u64 t, %1; cvt.u32.u64 %0, t; }"
        : "=r"(a) : "l"(p));
    return a;
}
__device__ __forceinline__ float expt(float s) {   // exp(10*s), shared w/ loss
    float e;
    asm("ex2.approx.ftz.f32 %0, %1;" : "=f"(e) : "f"(s * LOG2E10));
    return e;
}

#define CPA16(dst, src) \
    asm volatile("cp.async.cg.shared.global [%0], [%1], 16;" \
                 :: "r"(dst), "l"(src) : "memory")
#define CPA_COMMIT() asm volatile("cp.async.commit_group;" ::: "memory")
#define CPA_WAIT0()  asm volatile("cp.async.wait_group 0;" ::: "memory")

#define LDSM4(r0, r1, r2, r3, a) \
    asm volatile("ldmatrix.sync.aligned.m8n8.x4.shared.b16 {%0,%1,%2,%3}, [%4];" \
                 : "=r"(r0), "=r"(r1), "=r"(r2), "=r"(r3) : "r"(a))

__device__ __forceinline__ void mma16816(float* d, const uint32_t* a,
                                         uint32_t b0, uint32_t b1) {
    asm volatile(
        "mma.sync.aligned.m16n8k16.row.col.f32.bf16.bf16.f32 "
        "{%0,%1,%2,%3}, {%4,%5,%6,%7}, {%8,%9}, {%0,%1,%2,%3};"
        : "+f"(d[0]), "+f"(d[1]), "+f"(d[2]), "+f"(d[3])
        : "r"(a[0]), "r"(a[1]), "r"(a[2]), "r"(a[3]), "r"(b0), "r"(b1));
}

// ---- SMEM: A block + two B buffers, 128 rows x 272B each ----
#define BLKB  34816
#define SM_A   0
#define SM_B0  BLKB
#define SM_B1  (2 * BLKB)
#define SM_TOTAL (3 * BLKB)      // 104448

__device__ __forceinline__ void load_blk(uint32_t dst, int blk, int tid) {
    #pragma unroll
    for (int i = 0; i < 8; i++) {
        int idx = tid + i * 256;
        int r = idx >> 4, c = idx & 15;
        CPA16(dst + r * RSB + c * 16,
              g_zb + (size_t)(blk * 128 + r) * DDIM + c * 8);
    }
}

// ---------------------------------------------------------------------------
// Kernel 1: L2 normalize -> bf16 (one warp/row) + zero g_psum.
// ---------------------------------------------------------------------------
__global__ void norm_kernel(const float* __restrict__ xi,
                            const float* __restrict__ xj) {
    int gt = blockIdx.x * blockDim.x + threadIdx.x;
    if (gt < N2) g_psum[gt] = 0.f;

    int row  = blockIdx.x * 8 + (threadIdx.x >> 5);
    int lane = threadIdx.x & 31;
    const float* src = (row < BDIM) ? (xi + (size_t)row * DDIM)
                                    : (xj + (size_t)(row - BDIM) * DDIM);
    float4 v = reinterpret_cast<const float4*>(src)[lane];
    float s = v.x * v.x + v.y * v.y + v.z * v.z + v.w * v.w;
    #pragma unroll
    for (int o = 16; o > 0; o >>= 1) s += __shfl_xor_sync(0xFFFFFFFFu, s, o);
    float inv = 1.0f / fmaxf(sqrtf(s), 1e-12f);
    __nv_bfloat16 o4[4];
    o4[0] = __float2bfloat16(v.x * inv);
    o4[1] = __float2bfloat16(v.y * inv);
    o4[2] = __float2bfloat16(v.z * inv);
    o4[3] = __float2bfloat16(v.w * inv);
    *reinterpret_cast<uint2*>(g_zb + (size_t)row * DDIM + lane * 4) =
        *reinterpret_cast<uint2*>(o4);
}

// ---------------------------------------------------------------------------
// Kernel 2: persistent HMMA GEMM + fused exp row-sum epilogue.
// 148 CTAs; CTA p handles tiles [p*4096/148, (p+1)*4096/148), rb-major.
// 8 warps = 4 row-warps x 2 col-warps; warp tile 32x64, in 2 half-passes
// of 32 cols so ex2 (MUFU) overlaps next half's HMMA.
// ---------------------------------------------------------------------------
__global__ void __launch_bounds__(256, 1) simgemm_kernel() {
    extern __shared__ char smem[];
    const uint32_t sb = smem_u32(smem);
    const int tid  = threadIdx.x;
    const int lane = tid & 31;
    const int w    = tid >> 5;
    const int wr   = w & 3;
    const int wc   = w >> 2;

    const int rrow  = (lane & 7) + ((lane >> 3) & 1) * 8;
    const int csel  = lane >> 4;
    const int rquad = lane >> 2;
    const int cpair = (lane & 3) * 2;

    const int t0 = (int)(((long)blockIdx.x * TOT) / GRID);
    const int t1 = (int)(((long)(blockIdx.x + 1) * TOT) / GRID);

    int rb = t0 >> 6;
    load_blk(sb + SM_A, rb, tid);
    load_blk(sb + ((t0 & 1) ? SM_B1 : SM_B0), t0 & 63, tid);
    CPA_COMMIT();
    CPA_WAIT0();
    __syncthreads();

    uint32_t af[8][2][4];
    bool need_af = true;
    float rsum[4] = {0.f, 0.f, 0.f, 0.f};

    for (int t = t0; t < t1; t++) {
        const int ct = t & 63;

        bool fresh_af = false;
        if (need_af) {          // A fragments for this row-block (registers)
            #pragma unroll
            for (int ks = 0; ks < 8; ks++)
                #pragma unroll
                for (int i = 0; i < 2; i++) {
                    uint32_t a = sb + SM_A + (wr * 32 + i * 16 + rrow) * RSB
                               + (ks * 2 + csel) * 16;
                    LDSM4(af[ks][i][0], af[ks][i][1], af[ks][i][2], af[ks][i][3], a);
                }
            need_af = false;
            fresh_af = true;
        }

        // prefetch B(t+1) (and A of next row-block at segment boundary)
        if (t + 1 < t1) {
            const bool prefA = ((t + 1) >> 6) != rb;
            // race guard: if af was read from SM_A THIS iteration and we are
            // about to overwrite SM_A, make sure every warp's LDSM is done.
            if (prefA && fresh_af) __syncthreads();
            load_blk(sb + (((t + 1) & 1) ? SM_B1 : SM_B0), (t + 1) & 63, tid);
            if (prefA) load_blk(sb + SM_A, (t + 1) >> 6, tid);
            CPA_COMMIT();
        }

        const uint32_t sbB = sb + ((t & 1) ? SM_B1 : SM_B0);
        const bool isdiag = (ct == rb);
        const bool ispos  = (ct == (rb ^ 32));   // col == row ^ 4096
        const bool special = isdiag || ispos;

        // ---- two half-passes of 32 cols: MMA then exp, overlapped ----
        #pragma unroll
        for (int gp = 0; gp < 2; gp++) {
            uint32_t bfp[8][2][4];
            #pragma unroll
            for (int ks = 0; ks < 8; ks++)
                #pragma unroll
                for (int gs = 0; gs < 2; gs++) {
                    uint32_t a = sbB + (wc * 64 + gp * 32 + gs * 16 + rrow) * RSB
                               + (ks * 2 + csel) * 16;
                    LDSM4(bfp[ks][gs][0], bfp[ks][gs][1],
                          bfp[ks][gs][2], bfp[ks][gs][3], a);
                }
            float accp[2][4][4];
            #pragma unroll
            for (int i = 0; i < 2; i++)
                #pragma unroll
                for (int j = 0; j < 4; j++)
                    #pragma unroll
                    for (int c = 0; c < 4; c++) accp[i][j][c] = 0.f;
            #pragma unroll
            for (int ks = 0; ks < 8; ks++)
                #pragma unroll
                for (int i = 0; i < 2; i++)
                    #pragma unroll
                    for (int j = 0; j < 4; j++)
                        mma16816(accp[i][j], af[ks][i],
                                 bfp[ks][j >> 1][j & 1],
                                 bfp[ks][j >> 1][(j & 1) + 2]);

            if (special) {      // capture raw sim on local diagonal
                #pragma unroll
                for (int i = 0; i < 2; i++)
                    #pragma unroll
                    for (int j = 0; j < 4; j++)
                        #pragma unroll
                        for (int c = 0; c < 4; c++) {
                            int rl = wr * 32 + i * 16 + (c >> 1) * 8 + rquad;
                            int cl = wc * 64 + gp * 32 + j * 8 + cpair + (c & 1);
                            if (cl == rl) {
                                float s = accp[i][j][c];
                                if (isdiag) g_diag[rb * 128 + rl] = s;
                                if (ispos)  g_pos[rb * 128 + rl]  = s;
                            }
                        }
            }

            #pragma unroll
            for (int i = 0; i < 2; i++)
                #pragma unroll
                for (int j = 0; j < 4; j++)
                    #pragma unroll
                    for (int c = 0; c < 4; c++)
                        rsum[i * 2 + (c >> 1)] += expt(accp[i][j][c]);
        }

        // ---- segment end: flush row sums (atomics, <=2x per CTA) ----
        const bool segend = (t + 1 == t1) || (((t + 1) >> 6) != rb);
        if (segend) {
            #pragma unroll
            for (int qq = 0; qq < 4; qq++) {
                rsum[qq] += __shfl_xor_sync(0xFFFFFFFFu, rsum[qq], 1);
                rsum[qq] += __shfl_xor_sync(0xFFFFFFFFu, rsum[qq], 2);
            }
            if ((lane & 3) == 0) {
                #pragma unroll
                for (int qq = 0; qq < 4; qq++) {
                    int rl = wr * 32 + (qq >> 1) * 16 + (qq & 1) * 8 + rquad;
                    atomicAdd(&g_psum[rb * 128 + rl], rsum[qq]);
                }
            }
            #pragma unroll
            for (int qq = 0; qq < 4; qq++) rsum[qq] = 0.f;
        }

        if (t + 1 < t1) {
            CPA_WAIT0();
            __syncthreads();
            if (((t + 1) >> 6) != rb) { rb = (t + 1) >> 6; need_af = true; }
        }
    }
}

// ---------------------------------------------------------------------------
// Kernel 3: final scalar reduction.
// ---------------------------------------------------------------------------
__global__ void loss_kernel(float* __restrict__ out) {
    __shared__ float sred[1024];
    float s = 0.f;
    for (int r = threadIdx.x; r < N2; r += 1024) {
        float denom = g_psum[r] - expt(g_diag[r]);
        s += logf(denom) - g_pos[r] * 10.0f;
    }
    sred[threadIdx.x] = s;
    __syncthreads();
    for (int o = 512; o > 0; o >>= 1) {
        if (threadIdx.x < o) sred[threadIdx.x] += sred[threadIdx.x + o];
        __syncthreads();
    }
    if (threadIdx.x == 0) out[0] = sred[0] / (float)N2;
}

// ---------------------------------------------------------------------------
extern "C" void kernel_launch(void* const* d_in, const int* in_sizes, int n_in,
                              void* d_out, int out_size) {
    const float* xi = (const float*)d_in[0];
    const float* xj = (const float*)d_in[1];
    float* out = (float*)d_out;

    cudaFuncSetAttribute(simgemm_kernel,
                         cudaFuncAttributeMaxDynamicSharedMemorySize, SM_TOTAL);

    norm_kernel<<<N2 / 8, 256>>>(xi, xj);
    simgemm_kernel<<<GRID, 256, SM_TOTAL>>>();
    loss_kernel<<<1, 1024>>>(out);
}